// round 15
// baseline (speedup 1.0000x reference)
#include <cuda_runtime.h>
#include <cuda_fp16.h>
#include <cstdint>

#define D 128
#define N_NODES_MAX 50000
#define E_MAX 600000
#define AS_STRIDE 136   // fp16 elems per smem row (272B -> conflict-free ldmatrix)
#define HS_STRIDE 132   // fp16 elems per smem row for h staging (264B, 8B aligned)

// Scratch (device globals — no allocation allowed)
__device__ __half2 g_hh[N_NODES_MAX * (D / 2)];  // h = x @ W^T, fp16 (gather payload)
__device__ float g_ssrc[N_NODES_MAX];
__device__ float g_sdst[N_NODES_MAX];
__device__ int   g_cnt[N_NODES_MAX];        // ZERO invariant (module load; re-zeroed by scan_add)
__device__ int   g_off[N_NODES_MAX + 1];
__device__ int   g_cursor[N_NODES_MAX];
__device__ int   g_bsum[64];
__device__ int   g_srcs[E_MAX];

// ---------------- mma.sync helpers ----------------
__device__ __forceinline__ void ldm4(unsigned int& r0, unsigned int& r1,
                                     unsigned int& r2, unsigned int& r3,
                                     const void* p) {
    unsigned int addr = (unsigned int)__cvta_generic_to_shared(p);
    asm volatile("ldmatrix.sync.aligned.m8n8.x4.shared.b16 {%0,%1,%2,%3}, [%4];"
                 : "=r"(r0), "=r"(r1), "=r"(r2), "=r"(r3) : "r"(addr));
}
__device__ __forceinline__ void mma16816(float* c, const unsigned int* a,
                                         const unsigned int* b) {
    asm volatile("mma.sync.aligned.m16n8k16.row.col.f32.f16.f16.f32 "
                 "{%0,%1,%2,%3}, {%4,%5,%6,%7}, {%8,%9}, {%0,%1,%2,%3};"
                 : "+f"(c[0]), "+f"(c[1]), "+f"(c[2]), "+f"(c[3])
                 : "r"(a[0]), "r"(a[1]), "r"(a[2]), "r"(a[3]), "r"(b[0]), "r"(b[1]));
}

// ---------------------------------------------------------------------------
// 1) Histogram of dst — 4 edges/thread (fire-and-forget atomics -> REDG)
// ---------------------------------------------------------------------------
__global__ void hist_kernel(const int* __restrict__ ei, int E) {
    int t = blockIdx.x * blockDim.x + threadIdx.x;
    int e = t * 4;
    if (e + 4 <= E) {
        int4 d = *(const int4*)&ei[E + e];
        atomicAdd(&g_cnt[d.x], 1);
        atomicAdd(&g_cnt[d.y], 1);
        atomicAdd(&g_cnt[d.z], 1);
        atomicAdd(&g_cnt[d.w], 1);
    } else {
        for (int k = e; k < E; k++) atomicAdd(&g_cnt[ei[E + k]], 1);
    }
}

// ---------------------------------------------------------------------------
// 2a) Local exclusive scan per 1024-chunk
// ---------------------------------------------------------------------------
__global__ void scan_local_kernel(int N) {
    __shared__ int wsum[32];
    int tid = threadIdx.x;
    int i = blockIdx.x * 1024 + tid;
    int v = (i < N) ? g_cnt[i] : 0;
    int lane = tid & 31, wid = tid >> 5;
    int s = v;
    #pragma unroll
    for (int o = 1; o < 32; o <<= 1) {
        int t = __shfl_up_sync(0xffffffffu, s, o);
        if (lane >= o) s += t;
    }
    if (lane == 31) wsum[wid] = s;
    __syncthreads();
    if (wid == 0) {
        int ws = wsum[lane];
        #pragma unroll
        for (int o = 1; o < 32; o <<= 1) {
            int t = __shfl_up_sync(0xffffffffu, ws, o);
            if (lane >= o) ws += t;
        }
        wsum[lane] = ws;
    }
    __syncthreads();
    int excl = s - v + (wid ? wsum[wid - 1] : 0);
    if (i < N) g_off[i] = excl;
    if (tid == 1023) g_bsum[blockIdx.x] = excl + v;
}

// ---------------------------------------------------------------------------
// 2b) Add chunk prefix, init cursors, write g_off[N], re-zero g_cnt.
// ---------------------------------------------------------------------------
__global__ void scan_add_kernel(int N, int nb) {
    __shared__ int pre;
    int i = blockIdx.x * 256 + threadIdx.x;
    if (threadIdx.x == 0) {
        int seg = (blockIdx.x * 256) >> 10;
        int acc = 0;
        for (int b = 0; b < seg; b++) acc += g_bsum[b];
        pre = acc;
    }
    __syncthreads();
    if (i < N) {
        int c = g_cnt[i];
        int o = g_off[i] + pre;
        g_off[i] = o;
        g_cursor[i] = o;
        g_cnt[i] = 0;
        if (i == N - 1) g_off[N] = o + c;
    }
}

// ---------------------------------------------------------------------------
// 3) Scatter src ids into dst-sorted order — 4 edges/thread
// ---------------------------------------------------------------------------
__global__ void sort_kernel(const int* __restrict__ ei, int E) {
    int t = blockIdx.x * blockDim.x + threadIdx.x;
    int e = t * 4;
    if (e + 4 <= E) {
        int4 s = *(const int4*)&ei[e];
        int4 d = *(const int4*)&ei[E + e];
        int p0 = atomicAdd(&g_cursor[d.x], 1);
        int p1 = atomicAdd(&g_cursor[d.y], 1);
        int p2 = atomicAdd(&g_cursor[d.z], 1);
        int p3 = atomicAdd(&g_cursor[d.w], 1);
        g_srcs[p0] = s.x;
        g_srcs[p1] = s.y;
        g_srcs[p2] = s.z;
        g_srcs[p3] = s.w;
    } else {
        for (int k = e; k < E; k++) {
            int pos = atomicAdd(&g_cursor[ei[E + k]], 1);
            g_srcs[pos] = ei[k];
        }
    }
}

// ---------------------------------------------------------------------------
// 4) GEMM h = x @ W^T on tensor cores (mma.sync m16n8k16, fp16 in / fp32 acc).
// ---------------------------------------------------------------------------
__global__ __launch_bounds__(256, 1) void gemm_mma_kernel(
    const float* __restrict__ x, const float* __restrict__ W,
    const float* __restrict__ a, int N)
{
    extern __shared__ __half sm2[];
    __half* As = sm2;                               // 128 x AS_STRIDE
    __half* Bs = sm2 + 128 * AS_STRIDE;             // 128 x AS_STRIDE
    float* a_s = (float*)(sm2 + 2 * 128 * AS_STRIDE);  // 256 floats
    const int tid = threadIdx.x;
    const int row0 = blockIdx.x * 128;

    a_s[tid] = a[tid];

    const float4* x4 = (const float4*)x;
    const float4* W4 = (const float4*)W;
    #pragma unroll
    for (int i = 0; i < 16; i++) {
        int idx = tid + i * 256;
        int k4 = idx & 31, r = idx >> 5;
        float4 v = (row0 + r < N) ? x4[(row0 + r) * 32 + k4]
                                  : make_float4(0.f, 0.f, 0.f, 0.f);
        *(__half2*)&As[r * AS_STRIDE + k4 * 4]     = __floats2half2_rn(v.x, v.y);
        *(__half2*)&As[r * AS_STRIDE + k4 * 4 + 2] = __floats2half2_rn(v.z, v.w);
        float4 w = W4[idx];
        *(__half2*)&Bs[r * AS_STRIDE + k4 * 4]     = __floats2half2_rn(w.x, w.y);
        *(__half2*)&Bs[r * AS_STRIDE + k4 * 4 + 2] = __floats2half2_rn(w.z, w.w);
    }
    __syncthreads();

    const int wid = tid >> 5, lane = tid & 31;
    const int m_base = (wid & 3) * 32;
    const int n_base = (wid >> 2) * 64;

    float acc[2][8][4];
    #pragma unroll
    for (int tm = 0; tm < 2; tm++)
        #pragma unroll
        for (int tn = 0; tn < 8; tn++)
            #pragma unroll
            for (int c = 0; c < 4; c++) acc[tm][tn][c] = 0.f;

    const int lmA = (lane & 7) + ((lane >> 3) & 1) * 8;
    const int lkA = (lane >> 4) * 8;
    const int lnB = (lane & 7) + (lane >> 4) * 8;
    const int lkB = ((lane >> 3) & 1) * 8;

    #pragma unroll
    for (int ks = 0; ks < 8; ks++) {
        int k0 = ks * 16;
        unsigned int af[2][4];
        #pragma unroll
        for (int tm = 0; tm < 2; tm++)
            ldm4(af[tm][0], af[tm][1], af[tm][2], af[tm][3],
                 &As[(m_base + tm * 16 + lmA) * AS_STRIDE + k0 + lkA]);
        unsigned int bf[8][2];
        #pragma unroll
        for (int tp = 0; tp < 4; tp++) {
            unsigned int r0, r1, r2, r3;
            ldm4(r0, r1, r2, r3,
                 &Bs[(n_base + tp * 16 + lnB) * AS_STRIDE + k0 + lkB]);
            bf[tp * 2][0] = r0; bf[tp * 2][1] = r1;
            bf[tp * 2 + 1][0] = r2; bf[tp * 2 + 1][1] = r3;
        }
        #pragma unroll
        for (int tm = 0; tm < 2; tm++)
            #pragma unroll
            for (int tn = 0; tn < 8; tn++)
                mma16816(acc[tm][tn], af[tm], bf[tn]);
    }

    __syncthreads();
    __half* Hs = As;   // 128 x HS_STRIDE
    #pragma unroll
    for (int tm = 0; tm < 2; tm++) {
        int m = m_base + tm * 16 + (lane >> 2);
        #pragma unroll
        for (int tn = 0; tn < 8; tn++) {
            int n = n_base + tn * 8 + (lane & 3) * 2;
            *(__half2*)&Hs[m * HS_STRIDE + n] =
                __floats2half2_rn(acc[tm][tn][0], acc[tm][tn][1]);
            *(__half2*)&Hs[(m + 8) * HS_STRIDE + n] =
                __floats2half2_rn(acc[tm][tn][2], acc[tm][tn][3]);
        }
    }
    __syncthreads();

    #pragma unroll
    for (int i = 0; i < 16; i++) {
        int idx = tid + i * 256;
        int c = idx & 31, r = idx >> 5;
        if (row0 + r < N) {
            uint2 v = *(uint2*)&Hs[r * HS_STRIDE + c * 4];
            *(uint2*)&g_hh[(row0 + r) * 64 + c * 2] = v;
        }
    }

    {
        int r = tid & 127;
        const float* av = a_s + ((tid >= 128) ? 128 : 0);
        if (row0 + r < N) {
            float s = 0.f;
            #pragma unroll 8
            for (int j = 0; j < 64; j++) {
                float2 f = __half22float2(*(__half2*)&Hs[r * HS_STRIDE + j * 2]);
                s += f.x * av[2 * j] + f.y * av[2 * j + 1];
            }
            if (tid >= 128) g_sdst[row0 + r] = s;
            else            g_ssrc[row0 + r] = s;
        }
    }
}

// ---------------------------------------------------------------------------
// 5) Fused aggregate + residual + LayerNorm. One warp per node; main body
//    unrolled to 8 edges (8 independent idx loads -> 8 independent h-row +
//    ssrc loads in flight), then 4-chunk, then scalar tail.
// ---------------------------------------------------------------------------
__global__ __launch_bounds__(256) void agg_ln_kernel(
    const float* __restrict__ x, const float* __restrict__ gamma,
    const float* __restrict__ beta, float* __restrict__ out, int N)
{
    int gw = (blockIdx.x * blockDim.x + threadIdx.x) >> 5;
    int lane = threadIdx.x & 31;
    if (gw >= N) return;
    int start = g_off[gw];
    int end = g_off[gw + 1];
    float sdst = g_sdst[gw];

    const __half2* hh = g_hh;
    float a0 = 0.f, a1 = 0.f, a2 = 0.f, a3 = 0.f, z = 0.f;
    int e = start;
    for (; e + 8 <= end; e += 8) {
        int s0 = g_srcs[e + 0];
        int s1 = g_srcs[e + 1];
        int s2 = g_srcs[e + 2];
        int s3 = g_srcs[e + 3];
        int s4 = g_srcs[e + 4];
        int s5 = g_srcs[e + 5];
        int s6 = g_srcs[e + 6];
        int s7 = g_srcs[e + 7];
        uint2 r0 = *(const uint2*)&hh[s0 * (D / 2) + lane * 2];
        uint2 r1 = *(const uint2*)&hh[s1 * (D / 2) + lane * 2];
        uint2 r2 = *(const uint2*)&hh[s2 * (D / 2) + lane * 2];
        uint2 r3 = *(const uint2*)&hh[s3 * (D / 2) + lane * 2];
        uint2 r4 = *(const uint2*)&hh[s4 * (D / 2) + lane * 2];
        uint2 r5 = *(const uint2*)&hh[s5 * (D / 2) + lane * 2];
        uint2 r6 = *(const uint2*)&hh[s6 * (D / 2) + lane * 2];
        uint2 r7 = *(const uint2*)&hh[s7 * (D / 2) + lane * 2];
        float v0 = g_ssrc[s0] + sdst; v0 = v0 > 0.f ? v0 : 0.2f * v0;
        float v1 = g_ssrc[s1] + sdst; v1 = v1 > 0.f ? v1 : 0.2f * v1;
        float v2 = g_ssrc[s2] + sdst; v2 = v2 > 0.f ? v2 : 0.2f * v2;
        float v3 = g_ssrc[s3] + sdst; v3 = v3 > 0.f ? v3 : 0.2f * v3;
        float v4 = g_ssrc[s4] + sdst; v4 = v4 > 0.f ? v4 : 0.2f * v4;
        float v5 = g_ssrc[s5] + sdst; v5 = v5 > 0.f ? v5 : 0.2f * v5;
        float v6 = g_ssrc[s6] + sdst; v6 = v6 > 0.f ? v6 : 0.2f * v6;
        float v7 = g_ssrc[s7] + sdst; v7 = v7 > 0.f ? v7 : 0.2f * v7;
        float e0 = __expf(v0), e1 = __expf(v1), e2 = __expf(v2), e3 = __expf(v3);
        float e4 = __expf(v4), e5 = __expf(v5), e6 = __expf(v6), e7 = __expf(v7);
        z += ((e0 + e1) + (e2 + e3)) + ((e4 + e5) + (e6 + e7));
        float2 f0a = __half22float2(*(__half2*)&r0.x), f0b = __half22float2(*(__half2*)&r0.y);
        float2 f1a = __half22float2(*(__half2*)&r1.x), f1b = __half22float2(*(__half2*)&r1.y);
        float2 f2a = __half22float2(*(__half2*)&r2.x), f2b = __half22float2(*(__half2*)&r2.y);
        float2 f3a = __half22float2(*(__half2*)&r3.x), f3b = __half22float2(*(__half2*)&r3.y);
        float2 f4a = __half22float2(*(__half2*)&r4.x), f4b = __half22float2(*(__half2*)&r4.y);
        float2 f5a = __half22float2(*(__half2*)&r5.x), f5b = __half22float2(*(__half2*)&r5.y);
        float2 f6a = __half22float2(*(__half2*)&r6.x), f6b = __half22float2(*(__half2*)&r6.y);
        float2 f7a = __half22float2(*(__half2*)&r7.x), f7b = __half22float2(*(__half2*)&r7.y);
        a0 += (e0 * f0a.x + e1 * f1a.x + e2 * f2a.x + e3 * f3a.x)
            + (e4 * f4a.x + e5 * f5a.x + e6 * f6a.x + e7 * f7a.x);
        a1 += (e0 * f0a.y + e1 * f1a.y + e2 * f2a.y + e3 * f3a.y)
            + (e4 * f4a.y + e5 * f5a.y + e6 * f6a.y + e7 * f7a.y);
        a2 += (e0 * f0b.x + e1 * f1b.x + e2 * f2b.x + e3 * f3b.x)
            + (e4 * f4b.x + e5 * f5b.x + e6 * f6b.x + e7 * f7b.x);
        a3 += (e0 * f0b.y + e1 * f1b.y + e2 * f2b.y + e3 * f3b.y)
            + (e4 * f4b.y + e5 * f5b.y + e6 * f6b.y + e7 * f7b.y);
    }
    for (; e + 4 <= end; e += 4) {
        int s0 = g_srcs[e + 0];
        int s1 = g_srcs[e + 1];
        int s2 = g_srcs[e + 2];
        int s3 = g_srcs[e + 3];
        uint2 r0 = *(const uint2*)&hh[s0 * (D / 2) + lane * 2];
        uint2 r1 = *(const uint2*)&hh[s1 * (D / 2) + lane * 2];
        uint2 r2 = *(const uint2*)&hh[s2 * (D / 2) + lane * 2];
        uint2 r3 = *(const uint2*)&hh[s3 * (D / 2) + lane * 2];
        float v0 = g_ssrc[s0] + sdst; v0 = v0 > 0.f ? v0 : 0.2f * v0;
        float v1 = g_ssrc[s1] + sdst; v1 = v1 > 0.f ? v1 : 0.2f * v1;
        float v2 = g_ssrc[s2] + sdst; v2 = v2 > 0.f ? v2 : 0.2f * v2;
        float v3 = g_ssrc[s3] + sdst; v3 = v3 > 0.f ? v3 : 0.2f * v3;
        float e0 = __expf(v0), e1 = __expf(v1), e2 = __expf(v2), e3 = __expf(v3);
        z += (e0 + e1) + (e2 + e3);
        float2 f0a = __half22float2(*(__half2*)&r0.x), f0b = __half22float2(*(__half2*)&r0.y);
        float2 f1a = __half22float2(*(__half2*)&r1.x), f1b = __half22float2(*(__half2*)&r1.y);
        float2 f2a = __half22float2(*(__half2*)&r2.x), f2b = __half22float2(*(__half2*)&r2.y);
        float2 f3a = __half22float2(*(__half2*)&r3.x), f3b = __half22float2(*(__half2*)&r3.y);
        a0 += e0 * f0a.x + e1 * f1a.x + e2 * f2a.x + e3 * f3a.x;
        a1 += e0 * f0a.y + e1 * f1a.y + e2 * f2a.y + e3 * f3a.y;
        a2 += e0 * f0b.x + e1 * f1b.x + e2 * f2b.x + e3 * f3b.x;
        a3 += e0 * f0b.y + e1 * f1b.y + e2 * f2b.y + e3 * f3b.y;
    }
    for (; e < end; e++) {
        int s0 = g_srcs[e];
        uint2 r0 = *(const uint2*)&hh[s0 * (D / 2) + lane * 2];
        float v0 = g_ssrc[s0] + sdst; v0 = v0 > 0.f ? v0 : 0.2f * v0;
        float e0 = __expf(v0);
        z += e0;
        float2 f0a = __half22float2(*(__half2*)&r0.x), f0b = __half22float2(*(__half2*)&r0.y);
        a0 += e0 * f0a.x; a1 += e0 * f0a.y; a2 += e0 * f0b.x; a3 += e0 * f0b.y;
    }
    float invz = (end > start) ? 1.f / z : 0.f;

    float4 xv = *(const float4*)&x[gw * D + lane * 4];
    float y0 = a0 * invz + xv.x, y1 = a1 * invz + xv.y;
    float y2 = a2 * invz + xv.z, y3 = a3 * invz + xv.w;

    float s = y0 + y1 + y2 + y3;
    #pragma unroll
    for (int off = 16; off > 0; off >>= 1) s += __shfl_xor_sync(0xffffffffu, s, off);
    float mean = s * (1.f / 128.f);
    float d0 = y0 - mean, d1 = y1 - mean, d2 = y2 - mean, d3 = y3 - mean;
    float q = d0 * d0 + d1 * d1 + d2 * d2 + d3 * d3;
    #pragma unroll
    for (int off = 16; off > 0; off >>= 1) q += __shfl_xor_sync(0xffffffffu, q, off);
    float inv = rsqrtf(q * (1.f / 128.f) + 1e-5f);

    float4 gv = *(const float4*)&gamma[lane * 4];
    float4 bv = *(const float4*)&beta[lane * 4];
    float4 o;
    o.x = d0 * inv * gv.x + bv.x;
    o.y = d1 * inv * gv.y + bv.y;
    o.z = d2 * inv * gv.z + bv.z;
    o.w = d3 * inv * gv.w + bv.w;
    *(float4*)&out[gw * D + lane * 4] = o;
}

// ---------------------------------------------------------------------------
extern "C" void kernel_launch(void* const* d_in, const int* in_sizes, int n_in,
                              void* d_out, int out_size) {
    const float* x     = (const float*)d_in[0];
    const int*   ei    = (const int*)d_in[1];
    const float* W     = (const float*)d_in[2];
    const float* a     = (const float*)d_in[3];
    const float* gamma = (const float*)d_in[4];
    const float* beta  = (const float*)d_in[5];
    float* out = (float*)d_out;

    int N = in_sizes[0] / D;
    int E = in_sizes[1] / 2;
    int nb = (N + 1023) / 1024;
    int e4blocks = ((E + 3) / 4 + 255) / 256;

    static cudaStream_t s_side = nullptr;
    static cudaEvent_t ev_fork = nullptr, ev_join = nullptr;
    if (!s_side) {
        cudaStreamCreateWithFlags(&s_side, cudaStreamNonBlocking);
        cudaEventCreateWithFlags(&ev_fork, cudaEventDisableTiming);
        cudaEventCreateWithFlags(&ev_join, cudaEventDisableTiming);
    }

    int smem = 2 * 128 * AS_STRIDE * (int)sizeof(__half) + 256 * (int)sizeof(float);
    cudaFuncSetAttribute(gemm_mma_kernel, cudaFuncAttributeMaxDynamicSharedMemorySize, smem);

    cudaEventRecord(ev_fork, 0);
    cudaStreamWaitEvent(s_side, ev_fork, 0);
    hist_kernel<<<e4blocks, 256, 0, s_side>>>(ei, E);
    scan_local_kernel<<<nb, 1024, 0, s_side>>>(N);
    scan_add_kernel<<<(N + 255) / 256, 256, 0, s_side>>>(N, nb);
    sort_kernel<<<e4blocks, 256, 0, s_side>>>(ei, E);
    cudaEventRecord(ev_join, s_side);

    gemm_mma_kernel<<<(N + 127) / 128, 256, smem>>>(x, W, a, N);

    cudaStreamWaitEvent(0, ev_join, 0);
    agg_ln_kernel<<<(N * 32 + 255) / 256, 256>>>(x, gamma, beta, out, N);
}

// round 16
// speedup vs baseline: 1.1101x; 1.1101x over previous
#include <cuda_runtime.h>
#include <cuda_fp16.h>
#include <cstdint>

#define D 128
#define N_NODES_MAX 50000
#define E_MAX 600000
#define SLOT 48          // fixed bucket capacity per node (P(deg>48) ~ 1e-16)
#define OVF_CAP 8192
#define AS_STRIDE 136    // fp16 elems per smem row (272B -> conflict-free ldmatrix)
#define HS_STRIDE 132    // fp16 elems per smem row for h staging (264B, 8B aligned)

// Scratch (device globals — no allocation allowed)
__device__ __half2 g_hh[N_NODES_MAX * (D / 2)];  // h = x @ W^T, fp16 (gather payload)
__device__ float g_ssrc[N_NODES_MAX];
__device__ float g_sdst[N_NODES_MAX];
__device__ int   g_cnt[N_NODES_MAX];        // in-degree; ZERO invariant (module load;
                                            // re-zeroed by agg_ln each launch)
__device__ int   g_bk[N_NODES_MAX * SLOT];  // bucketed src ids
__device__ int   g_ovf_cnt;                 // overflow count (re-zeroed by agg_ln)
__device__ int   g_ovf_src[OVF_CAP];
__device__ int   g_ovf_dst[OVF_CAP];

// ---------------- mma.sync helpers ----------------
__device__ __forceinline__ void ldm4(unsigned int& r0, unsigned int& r1,
                                     unsigned int& r2, unsigned int& r3,
                                     const void* p) {
    unsigned int addr = (unsigned int)__cvta_generic_to_shared(p);
    asm volatile("ldmatrix.sync.aligned.m8n8.x4.shared.b16 {%0,%1,%2,%3}, [%4];"
                 : "=r"(r0), "=r"(r1), "=r"(r2), "=r"(r3) : "r"(addr));
}
__device__ __forceinline__ void mma16816(float* c, const unsigned int* a,
                                         const unsigned int* b) {
    asm volatile("mma.sync.aligned.m16n8k16.row.col.f32.f16.f16.f32 "
                 "{%0,%1,%2,%3}, {%4,%5,%6,%7}, {%8,%9}, {%0,%1,%2,%3};"
                 : "+f"(c[0]), "+f"(c[1]), "+f"(c[2]), "+f"(c[3])
                 : "r"(a[0]), "r"(a[1]), "r"(a[2]), "r"(a[3]), "r"(b[0]), "r"(b[1]));
}

// ---------------------------------------------------------------------------
// 1) Bucket edges directly: rank = atomicAdd(cnt[dst]); bk[dst*SLOT+rank]=src.
//    Replaces hist + scan_local + scan_add + sort (no CSR needed).
//    4 edges/thread: 4 independent ATOMG->STG chains.
// ---------------------------------------------------------------------------
__device__ __forceinline__ void bucket_one(int src, int dst) {
    int r = atomicAdd(&g_cnt[dst], 1);
    if (r < SLOT) {
        g_bk[dst * SLOT + r] = src;
    } else {
        int p = atomicAdd(&g_ovf_cnt, 1);
        if (p < OVF_CAP) { g_ovf_src[p] = src; g_ovf_dst[p] = dst; }
    }
}
__global__ void bucket_kernel(const int* __restrict__ ei, int E) {
    int t = blockIdx.x * blockDim.x + threadIdx.x;
    int e = t * 4;
    if (e + 4 <= E) {
        int4 s = *(const int4*)&ei[e];
        int4 d = *(const int4*)&ei[E + e];
        bucket_one(s.x, d.x);
        bucket_one(s.y, d.y);
        bucket_one(s.z, d.z);
        bucket_one(s.w, d.w);
    } else {
        for (int k = e; k < E; k++) bucket_one(ei[k], ei[E + k]);
    }
}

// ---------------------------------------------------------------------------
// 2) GEMM h = x @ W^T on tensor cores (mma.sync m16n8k16, fp16 in / fp32 acc).
// ---------------------------------------------------------------------------
__global__ __launch_bounds__(256, 1) void gemm_mma_kernel(
    const float* __restrict__ x, const float* __restrict__ W,
    const float* __restrict__ a, int N)
{
    extern __shared__ __half sm2[];
    __half* As = sm2;                               // 128 x AS_STRIDE
    __half* Bs = sm2 + 128 * AS_STRIDE;             // 128 x AS_STRIDE
    float* a_s = (float*)(sm2 + 2 * 128 * AS_STRIDE);  // 256 floats
    const int tid = threadIdx.x;
    const int row0 = blockIdx.x * 128;

    a_s[tid] = a[tid];

    const float4* x4 = (const float4*)x;
    const float4* W4 = (const float4*)W;
    #pragma unroll
    for (int i = 0; i < 16; i++) {
        int idx = tid + i * 256;
        int k4 = idx & 31, r = idx >> 5;
        float4 v = (row0 + r < N) ? x4[(row0 + r) * 32 + k4]
                                  : make_float4(0.f, 0.f, 0.f, 0.f);
        *(__half2*)&As[r * AS_STRIDE + k4 * 4]     = __floats2half2_rn(v.x, v.y);
        *(__half2*)&As[r * AS_STRIDE + k4 * 4 + 2] = __floats2half2_rn(v.z, v.w);
        float4 w = W4[idx];
        *(__half2*)&Bs[r * AS_STRIDE + k4 * 4]     = __floats2half2_rn(w.x, w.y);
        *(__half2*)&Bs[r * AS_STRIDE + k4 * 4 + 2] = __floats2half2_rn(w.z, w.w);
    }
    __syncthreads();

    const int wid = tid >> 5, lane = tid & 31;
    const int m_base = (wid & 3) * 32;
    const int n_base = (wid >> 2) * 64;

    float acc[2][8][4];
    #pragma unroll
    for (int tm = 0; tm < 2; tm++)
        #pragma unroll
        for (int tn = 0; tn < 8; tn++)
            #pragma unroll
            for (int c = 0; c < 4; c++) acc[tm][tn][c] = 0.f;

    const int lmA = (lane & 7) + ((lane >> 3) & 1) * 8;
    const int lkA = (lane >> 4) * 8;
    const int lnB = (lane & 7) + (lane >> 4) * 8;
    const int lkB = ((lane >> 3) & 1) * 8;

    #pragma unroll
    for (int ks = 0; ks < 8; ks++) {
        int k0 = ks * 16;
        unsigned int af[2][4];
        #pragma unroll
        for (int tm = 0; tm < 2; tm++)
            ldm4(af[tm][0], af[tm][1], af[tm][2], af[tm][3],
                 &As[(m_base + tm * 16 + lmA) * AS_STRIDE + k0 + lkA]);
        unsigned int bf[8][2];
        #pragma unroll
        for (int tp = 0; tp < 4; tp++) {
            unsigned int r0, r1, r2, r3;
            ldm4(r0, r1, r2, r3,
                 &Bs[(n_base + tp * 16 + lnB) * AS_STRIDE + k0 + lkB]);
            bf[tp * 2][0] = r0; bf[tp * 2][1] = r1;
            bf[tp * 2 + 1][0] = r2; bf[tp * 2 + 1][1] = r3;
        }
        #pragma unroll
        for (int tm = 0; tm < 2; tm++)
            #pragma unroll
            for (int tn = 0; tn < 8; tn++)
                mma16816(acc[tm][tn], af[tm], bf[tn]);
    }

    __syncthreads();
    __half* Hs = As;   // 128 x HS_STRIDE
    #pragma unroll
    for (int tm = 0; tm < 2; tm++) {
        int m = m_base + tm * 16 + (lane >> 2);
        #pragma unroll
        for (int tn = 0; tn < 8; tn++) {
            int n = n_base + tn * 8 + (lane & 3) * 2;
            *(__half2*)&Hs[m * HS_STRIDE + n] =
                __floats2half2_rn(acc[tm][tn][0], acc[tm][tn][1]);
            *(__half2*)&Hs[(m + 8) * HS_STRIDE + n] =
                __floats2half2_rn(acc[tm][tn][2], acc[tm][tn][3]);
        }
    }
    __syncthreads();

    #pragma unroll
    for (int i = 0; i < 16; i++) {
        int idx = tid + i * 256;
        int c = idx & 31, r = idx >> 5;
        if (row0 + r < N) {
            uint2 v = *(uint2*)&Hs[r * HS_STRIDE + c * 4];
            *(uint2*)&g_hh[(row0 + r) * 64 + c * 2] = v;
        }
    }

    {
        int r = tid & 127;
        const float* av = a_s + ((tid >= 128) ? 128 : 0);
        if (row0 + r < N) {
            float s = 0.f;
            #pragma unroll 8
            for (int j = 0; j < 64; j++) {
                float2 f = __half22float2(*(__half2*)&Hs[r * HS_STRIDE + j * 2]);
                s += f.x * av[2 * j] + f.y * av[2 * j + 1];
            }
            if (tid >= 128) g_sdst[row0 + r] = s;
            else            g_ssrc[row0 + r] = s;
        }
    }
}

// ---------------------------------------------------------------------------
// 3) Fused aggregate + residual + LayerNorm (R14 loop body; bucket indexing).
//    Also restores the ZERO invariant on g_cnt / g_ovf_cnt for the next call.
// ---------------------------------------------------------------------------
__global__ __launch_bounds__(256) void agg_ln_kernel(
    const float* __restrict__ x, const float* __restrict__ gamma,
    const float* __restrict__ beta, float* __restrict__ out, int N)
{
    int gw = (blockIdx.x * blockDim.x + threadIdx.x) >> 5;
    int lane = threadIdx.x & 31;
    if (gw >= N) return;
    int deg = g_cnt[gw];                         // broadcast load
    int start = gw * SLOT;
    int end = start + min(deg, SLOT);
    float sdst = g_sdst[gw];

    const __half2* hh = g_hh;
    float a0 = 0.f, a1 = 0.f, a2 = 0.f, a3 = 0.f, z = 0.f;
    int e = start;
    for (; e + 4 <= end; e += 4) {
        int s0 = g_bk[e + 0];
        int s1 = g_bk[e + 1];
        int s2 = g_bk[e + 2];
        int s3 = g_bk[e + 3];
        uint2 r0 = *(const uint2*)&hh[s0 * (D / 2) + lane * 2];
        uint2 r1 = *(const uint2*)&hh[s1 * (D / 2) + lane * 2];
        uint2 r2 = *(const uint2*)&hh[s2 * (D / 2) + lane * 2];
        uint2 r3 = *(const uint2*)&hh[s3 * (D / 2) + lane * 2];
        float v0 = g_ssrc[s0] + sdst; v0 = v0 > 0.f ? v0 : 0.2f * v0;
        float v1 = g_ssrc[s1] + sdst; v1 = v1 > 0.f ? v1 : 0.2f * v1;
        float v2 = g_ssrc[s2] + sdst; v2 = v2 > 0.f ? v2 : 0.2f * v2;
        float v3 = g_ssrc[s3] + sdst; v3 = v3 > 0.f ? v3 : 0.2f * v3;
        float e0 = __expf(v0), e1 = __expf(v1), e2 = __expf(v2), e3 = __expf(v3);
        z += (e0 + e1) + (e2 + e3);
        float2 f0a = __half22float2(*(__half2*)&r0.x), f0b = __half22float2(*(__half2*)&r0.y);
        float2 f1a = __half22float2(*(__half2*)&r1.x), f1b = __half22float2(*(__half2*)&r1.y);
        float2 f2a = __half22float2(*(__half2*)&r2.x), f2b = __half22float2(*(__half2*)&r2.y);
        float2 f3a = __half22float2(*(__half2*)&r3.x), f3b = __half22float2(*(__half2*)&r3.y);
        a0 += e0 * f0a.x + e1 * f1a.x + e2 * f2a.x + e3 * f3a.x;
        a1 += e0 * f0a.y + e1 * f1a.y + e2 * f2a.y + e3 * f3a.y;
        a2 += e0 * f0b.x + e1 * f1b.x + e2 * f2b.x + e3 * f3b.x;
        a3 += e0 * f0b.y + e1 * f1b.y + e2 * f2b.y + e3 * f3b.y;
    }
    for (; e < end; e++) {
        int s0 = g_bk[e];
        uint2 r0 = *(const uint2*)&hh[s0 * (D / 2) + lane * 2];
        float v0 = g_ssrc[s0] + sdst; v0 = v0 > 0.f ? v0 : 0.2f * v0;
        float e0 = __expf(v0);
        z += e0;
        float2 f0a = __half22float2(*(__half2*)&r0.x), f0b = __half22float2(*(__half2*)&r0.y);
        a0 += e0 * f0a.x; a1 += e0 * f0a.y; a2 += e0 * f0b.x; a3 += e0 * f0b.y;
    }
    // Overflow edges (deg > SLOT): astronomically rare; correctness path.
    if (deg > SLOT) {
        int oc = g_ovf_cnt;
        if (oc > OVF_CAP) oc = OVF_CAP;
        for (int i = 0; i < oc; i++) {
            if (g_ovf_dst[i] == gw) {
                int s0 = g_ovf_src[i];
                uint2 r0 = *(const uint2*)&hh[s0 * (D / 2) + lane * 2];
                float v0 = g_ssrc[s0] + sdst; v0 = v0 > 0.f ? v0 : 0.2f * v0;
                float e0 = __expf(v0);
                z += e0;
                float2 f0a = __half22float2(*(__half2*)&r0.x);
                float2 f0b = __half22float2(*(__half2*)&r0.y);
                a0 += e0 * f0a.x; a1 += e0 * f0a.y; a2 += e0 * f0b.x; a3 += e0 * f0b.y;
            }
        }
    }
    float invz = (deg > 0) ? 1.f / z : 0.f;

    // Restore ZERO invariant for the next launch/replay.
    if (lane == 0) {
        g_cnt[gw] = 0;
        if (gw == 0) g_ovf_cnt = 0;
    }

    float4 xv = *(const float4*)&x[gw * D + lane * 4];
    float y0 = a0 * invz + xv.x, y1 = a1 * invz + xv.y;
    float y2 = a2 * invz + xv.z, y3 = a3 * invz + xv.w;

    float s = y0 + y1 + y2 + y3;
    #pragma unroll
    for (int off = 16; off > 0; off >>= 1) s += __shfl_xor_sync(0xffffffffu, s, off);
    float mean = s * (1.f / 128.f);
    float d0 = y0 - mean, d1 = y1 - mean, d2 = y2 - mean, d3 = y3 - mean;
    float q = d0 * d0 + d1 * d1 + d2 * d2 + d3 * d3;
    #pragma unroll
    for (int off = 16; off > 0; off >>= 1) q += __shfl_xor_sync(0xffffffffu, q, off);
    float inv = rsqrtf(q * (1.f / 128.f) + 1e-5f);

    float4 gv = *(const float4*)&gamma[lane * 4];
    float4 bv = *(const float4*)&beta[lane * 4];
    float4 o;
    o.x = d0 * inv * gv.x + bv.x;
    o.y = d1 * inv * gv.y + bv.y;
    o.z = d2 * inv * gv.z + bv.z;
    o.w = d3 * inv * gv.w + bv.w;
    *(float4*)&out[gw * D + lane * 4] = o;
}

// ---------------------------------------------------------------------------
extern "C" void kernel_launch(void* const* d_in, const int* in_sizes, int n_in,
                              void* d_out, int out_size) {
    const float* x     = (const float*)d_in[0];
    const int*   ei    = (const int*)d_in[1];
    const float* W     = (const float*)d_in[2];
    const float* a     = (const float*)d_in[3];
    const float* gamma = (const float*)d_in[4];
    const float* beta  = (const float*)d_in[5];
    float* out = (float*)d_out;

    int N = in_sizes[0] / D;
    int E = in_sizes[1] / 2;
    int e4blocks = ((E + 3) / 4 + 255) / 256;

    static cudaStream_t s_side = nullptr;
    static cudaEvent_t ev_fork = nullptr, ev_join = nullptr;
    if (!s_side) {
        cudaStreamCreateWithFlags(&s_side, cudaStreamNonBlocking);
        cudaEventCreateWithFlags(&ev_fork, cudaEventDisableTiming);
        cudaEventCreateWithFlags(&ev_join, cudaEventDisableTiming);
    }

    int smem = 2 * 128 * AS_STRIDE * (int)sizeof(__half) + 256 * (int)sizeof(float);
    cudaFuncSetAttribute(gemm_mma_kernel, cudaFuncAttributeMaxDynamicSharedMemorySize, smem);

    cudaEventRecord(ev_fork, 0);
    cudaStreamWaitEvent(s_side, ev_fork, 0);
    bucket_kernel<<<e4blocks, 256, 0, s_side>>>(ei, E);
    cudaEventRecord(ev_join, s_side);

    gemm_mma_kernel<<<(N + 127) / 128, 256, smem>>>(x, W, a, N);

    cudaStreamWaitEvent(0, ev_join, 0);
    agg_ln_kernel<<<(N * 32 + 255) / 256, 256>>>(x, gamma, beta, out, N);
}